// round 1
// baseline (speedup 1.0000x reference)
#include <cuda_runtime.h>
#include <cuda_bf16.h>
#include <math.h>

#define MAXN 100000
#define MAXE 1600000

// ---------------- scratch (static device globals; no allocation) ----------------
__device__ float g_z[MAXN * 64];        // h @ W_fc^T
__device__ float g_df[MAXN * 64];       // feat @ W_dst^T
__device__ float g_Wt[256 * 64];        // W_fc transposed  [K][O]
__device__ float g_Wdt[64 * 64];        // W_dst transposed [K][O]
__device__ int   g_cnt[MAXN];
__device__ int   g_off[MAXN + 1];
__device__ int   g_cur[MAXN];
__device__ int   g_src32[MAXE];
__device__ int   g_dst32[MAXE];
__device__ int   g_ssrc[MAXE];          // src ids grouped by dst (CSR payload)
__device__ int   g_is64;

// ---------------- index dtype detection + conversion ----------------
__global__ void detect_kernel(const void* dstp, int e, int n) {
    __shared__ int bad;
    if (threadIdx.x == 0) bad = 0;
    __syncthreads();
    const long long* p = (const long long*)dstp;
    int lim = e < 2048 ? e / 2 : 2048;  // never read past e*4 bytes
    for (int i = threadIdx.x; i < lim; i += blockDim.x) {
        long long v = p[i];
        if (v < 0 || v >= (long long)n) bad = 1;
    }
    __syncthreads();
    if (threadIdx.x == 0) g_is64 = !bad;
}

__global__ void convert_kernel(const void* src, const void* dst, int e) {
    int i = blockIdx.x * blockDim.x + threadIdx.x;
    if (i >= e) return;
    if (g_is64) {
        g_src32[i] = (int)((const long long*)src)[i];
        g_dst32[i] = (int)((const long long*)dst)[i];
    } else {
        g_src32[i] = ((const int*)src)[i];
        g_dst32[i] = ((const int*)dst)[i];
    }
}

// ---------------- weight transposes ----------------
__global__ void transpose_kernel(const float* __restrict__ Wfc, const float* __restrict__ Wdst) {
    int i = blockIdx.x * blockDim.x + threadIdx.x;
    if (i < 64 * 256) { int o = i / 256, k = i % 256; g_Wt[k * 64 + o] = Wfc[i]; }
    if (i < 64 * 64)  { int o = i / 64,  k = i % 64;  g_Wdt[k * 64 + o] = Wdst[i]; }
}

// ---------------- tiled fp32 GEMM: C[M,64] = A[M,K] * B[K,64] ----------------
template <int K>
__device__ __forceinline__ void gemm64_body(const float* __restrict__ A,
                                            const float* __restrict__ B,
                                            float* __restrict__ C, int M) {
    constexpr int BK = 16;
    __shared__ float As[64][BK + 1];   // +1 pad: kill bank conflicts on column reads
    __shared__ float Bs[BK][64];
    const int tid = threadIdx.x;
    const int tx = tid & 15;           // output-col group (4 cols)
    const int ty = tid >> 4;           // row group (4 rows)
    const int row0 = blockIdx.x * 64;

    float acc[4][4];
#pragma unroll
    for (int i = 0; i < 4; i++)
#pragma unroll
        for (int j = 0; j < 4; j++) acc[i][j] = 0.f;

    for (int k0 = 0; k0 < K; k0 += BK) {
        // A tile: 64 x BK  (256 float4 loads)
        {
            int r = tid >> 2;
            int c = (tid & 3) * 4;
            int gr = row0 + r;
            float4 v = make_float4(0.f, 0.f, 0.f, 0.f);
            if (gr < M) v = *(const float4*)(A + (size_t)gr * K + k0 + c);
            As[r][c + 0] = v.x; As[r][c + 1] = v.y; As[r][c + 2] = v.z; As[r][c + 3] = v.w;
        }
        // B tile: BK x 64
        {
            int r = tid >> 4;
            int c = (tid & 15) * 4;
            float4 v = *(const float4*)(B + (size_t)(k0 + r) * 64 + c);
            *(float4*)&Bs[r][c] = v;
        }
        __syncthreads();
#pragma unroll
        for (int kk = 0; kk < BK; kk++) {
            float a0 = As[ty * 4 + 0][kk];
            float a1 = As[ty * 4 + 1][kk];
            float a2 = As[ty * 4 + 2][kk];
            float a3 = As[ty * 4 + 3][kk];
            float4 b = *(const float4*)&Bs[kk][tx * 4];
            acc[0][0] += a0 * b.x; acc[0][1] += a0 * b.y; acc[0][2] += a0 * b.z; acc[0][3] += a0 * b.w;
            acc[1][0] += a1 * b.x; acc[1][1] += a1 * b.y; acc[1][2] += a1 * b.z; acc[1][3] += a1 * b.w;
            acc[2][0] += a2 * b.x; acc[2][1] += a2 * b.y; acc[2][2] += a2 * b.z; acc[2][3] += a2 * b.w;
            acc[3][0] += a3 * b.x; acc[3][1] += a3 * b.y; acc[3][2] += a3 * b.z; acc[3][3] += a3 * b.w;
        }
        __syncthreads();
    }
#pragma unroll
    for (int i = 0; i < 4; i++) {
        int gr = row0 + ty * 4 + i;
        if (gr < M) {
            float4 v = make_float4(acc[i][0], acc[i][1], acc[i][2], acc[i][3]);
            *(float4*)(C + (size_t)gr * 64 + tx * 4) = v;
        }
    }
}

__global__ void gemm_z_kernel(const float* __restrict__ h, int M) {
    gemm64_body<256>(h, g_Wt, g_z, M);
}
__global__ void gemm_df_kernel(const float* __restrict__ f, int M) {
    gemm64_body<64>(f, g_Wdt, g_df, M);
}

// ---------------- CSR construction ----------------
__global__ void zero_cnt_kernel(int n) {
    int i = blockIdx.x * blockDim.x + threadIdx.x;
    if (i < n) g_cnt[i] = 0;
}

__global__ void hist_kernel(int e) {
    int i = blockIdx.x * blockDim.x + threadIdx.x;
    if (i < e) atomicAdd(&g_cnt[g_dst32[i]], 1);
}

// single-block exclusive scan of g_cnt[0..n) -> g_off; g_off[n] = total
__global__ void scan_kernel(int n) {
    __shared__ int sh[1024];
    __shared__ int carry;
    const int tid = threadIdx.x;
    if (tid == 0) carry = 0;
    __syncthreads();
    for (int base = 0; base < n; base += 1024) {
        int v = (base + tid < n) ? g_cnt[base + tid] : 0;
        sh[tid] = v;
        __syncthreads();
#pragma unroll
        for (int s = 1; s < 1024; s <<= 1) {
            int t = (tid >= s) ? sh[tid - s] : 0;
            __syncthreads();
            sh[tid] += t;
            __syncthreads();
        }
        if (base + tid < n) g_off[base + tid] = carry + sh[tid] - v;
        __syncthreads();
        if (tid == 0) carry += sh[1023];
        __syncthreads();
    }
    if (tid == 0) g_off[n] = carry;
}

__global__ void copy_cur_kernel(int n) {
    int i = blockIdx.x * blockDim.x + threadIdx.x;
    if (i < n) g_cur[i] = g_off[i];
}

__global__ void scatter_kernel(int e) {
    int i = blockIdx.x * blockDim.x + threadIdx.x;
    if (i >= e) return;
    int d = g_dst32[i];
    int slot = atomicAdd(&g_cur[d], 1);
    g_ssrc[slot] = g_src32[i];
}

// ---------------- aggregation: one warp per dst node, online softmax ----------------
__global__ void aggregate_kernel(float* __restrict__ out, int n) {
    int warp = (blockIdx.x * blockDim.x + threadIdx.x) >> 5;
    int lane = threadIdx.x & 31;
    if (warp >= n) return;

    const float2 dfl = *(const float2*)&g_df[(size_t)warp * 64 + lane * 2];
    const int s0 = g_off[warp];
    const int s1 = g_off[warp + 1];

    float m = -INFINITY, d = 0.f;
    float2 acc = make_float2(0.f, 0.f);

    for (int s = s0; s < s1; s++) {
        int src = g_ssrc[s];
        float2 zl = *(const float2*)&g_z[(size_t)src * 64 + lane * 2];
        float p = zl.x * dfl.x + zl.y * dfl.y;
#pragma unroll
        for (int o = 16; o; o >>= 1) p += __shfl_xor_sync(0xffffffffu, p, o);
        float mn = fmaxf(m, p);
        float sc = __expf(m - mn);      // exp(-inf)=0 handles first edge
        float w  = __expf(p - mn);
        d = d * sc + w;
        acc.x = acc.x * sc + w * zl.x;
        acc.y = acc.y * sc + w * zl.y;
        m = mn;
    }
    float inv = 1.f / (d == 0.f ? 1.f : d);
    float2 o2 = make_float2(acc.x * inv, acc.y * inv);
    *(float2*)&out[(size_t)warp * 64 + lane * 2] = o2;
}

// ---------------- launch ----------------
extern "C" void kernel_launch(void* const* d_in, const int* in_sizes, int n_in,
                              void* d_out, int out_size) {
    const float* h    = (const float*)d_in[0];
    const float* feat = (const float*)d_in[1];
    const float* Wfc  = (const float*)d_in[2];
    const float* Wdst = (const float*)d_in[3];
    const void*  src  = d_in[4];
    const void*  dst  = d_in[5];
    float* out = (float*)d_out;

    const int N = in_sizes[0] / 256;
    const int E = in_sizes[4];

    detect_kernel<<<1, 256>>>(dst, E, N);
    convert_kernel<<<(E + 255) / 256, 256>>>(src, dst, E);
    transpose_kernel<<<(64 * 256 + 255) / 256, 256>>>(Wfc, Wdst);

    gemm_z_kernel<<<(N + 63) / 64, 256>>>(h, N);
    gemm_df_kernel<<<(N + 63) / 64, 256>>>(feat, N);

    zero_cnt_kernel<<<(N + 255) / 256, 256>>>(N);
    hist_kernel<<<(E + 255) / 256, 256>>>(E);
    scan_kernel<<<1, 1024>>>(N);
    copy_cur_kernel<<<(N + 255) / 256, 256>>>(N);
    scatter_kernel<<<(E + 255) / 256, 256>>>(E);

    aggregate_kernel<<<(N + 7) / 8, 256>>>(out, N);
}